// round 1
// baseline (speedup 1.0000x reference)
#include <cuda_runtime.h>
#include <math.h>

#define TT    16384
#define AA    128
#define KK    128
#define NROW  4
#define NSTEP 16
#define EE    126

// ---------------- device scratch (static: no allocations allowed) ----------
__device__ float g_du[AA * KK];            // normalized dictionary
__device__ float g_xc[AA * AA * 256];      // atom cross-correlation, stride 256 (j in [0,255))
__device__ float g_fm[NROW * AA * TT];     // feature maps (4 rows = 2 signals x 2 batches)
__device__ float g_res[NROW * TT];         // residuals
__device__ float g_cm[NROW * TT];          // per-column max over atoms
__device__ float g_emb[NROW * NSTEP * 128];// embeddings per step

// ---------------- prep: d_unit + residual init -----------------------------
__global__ void prep_kernel(const float* __restrict__ a,
                            const float* __restrict__ b,
                            const float* __restrict__ d)
{
    __shared__ float sred[4];
    int bx = blockIdx.x;
    int tid = threadIdx.x; // 128
    if (bx < AA) {
        float v = d[bx * KK + tid];
        float ss = v * v;
        #pragma unroll
        for (int off = 16; off; off >>= 1)
            ss += __shfl_down_sync(0xffffffffu, ss, off);
        if ((tid & 31) == 0) sred[tid >> 5] = ss;
        __syncthreads();
        float tot = sred[0] + sred[1] + sred[2] + sred[3];
        g_du[bx * KK + tid] = v / (sqrtf(tot) + 1e-8f);
    } else {
        int base = (bx - AA) * 256;
        #pragma unroll
        for (int j = tid; j < 256; j += 128) {
            int i = base + j;
            g_res[i] = (i < 2 * TT) ? a[i] : b[i - 2 * TT];
        }
    }
}

// ---------------- generic correlation kernel -------------------------------
// out[a][t] = sum_k src[t0 + c - shift + k] * du[a][k]
// mode 0: fm   (src = g_res row, srcLen=TT, shift=64,  outStride=TT)
// mode 1: xcorr(src = g_du row,  srcLen=KK, shift=127, outStride=256)
__global__ __launch_bounds__(256) void corr_kernel(int mode)
{
    __shared__ float s_du[KK][64];   // [k][a_local] 32KB
    __shared__ float s_sig[256];

    int t0   = blockIdx.x * 128;
    int row  = blockIdx.y;
    int half = blockIdx.z;
    int tid  = threadIdx.x; // 256

    for (int i = tid; i < 64 * KK; i += 256) {
        int al = i >> 7, k = i & 127;
        s_du[k][al] = g_du[(half * 64 + al) * KK + k];
    }

    const float* src;
    float* out;
    int srcLen, shift, outStride;
    if (mode == 0) {
        src = g_res + row * TT; srcLen = TT; shift = 64;
        out = g_fm + row * AA * TT; outStride = TT;
    } else {
        src = g_du + row * KK; srcLen = KK; shift = 127;
        out = g_xc + row * AA * 256; outStride = 256;
    }

    for (int j = tid; j < 256; j += 256) {
        int t = t0 + j - shift;
        s_sig[j] = (t >= 0 && t < srcLen) ? src[t] : 0.f;
    }
    __syncthreads();

    int x = tid & 31, y = tid >> 5;
    int c0 = x * 4, a0 = y * 8;

    float acc[8][4];
    #pragma unroll
    for (int j = 0; j < 8; j++) {
        acc[j][0] = 0.f; acc[j][1] = 0.f; acc[j][2] = 0.f; acc[j][3] = 0.f;
    }

    float r0 = s_sig[c0], r1 = s_sig[c0 + 1], r2 = s_sig[c0 + 2], r3 = s_sig[c0 + 3];

    #pragma unroll 4
    for (int k = 0; k < KK; k++) {
        float dv[8];
        #pragma unroll
        for (int j = 0; j < 8; j++) dv[j] = s_du[k][a0 + j];
        #pragma unroll
        for (int j = 0; j < 8; j++) {
            acc[j][0] += dv[j] * r0;
            acc[j][1] += dv[j] * r1;
            acc[j][2] += dv[j] * r2;
            acc[j][3] += dv[j] * r3;
        }
        r0 = r1; r1 = r2; r2 = r3;
        r3 = s_sig[c0 + 4 + k];   // max index 124+4+127 = 255, in bounds
    }

    int a_base = half * 64 + a0;
    int t = t0 + c0;
    #pragma unroll
    for (int j = 0; j < 8; j++) {
        float4 v4 = make_float4(acc[j][0], acc[j][1], acc[j][2], acc[j][3]);
        *(float4*)(out + (a_base + j) * outStride + t) = v4;
    }
}

// ---------------- column max over atoms ------------------------------------
__global__ __launch_bounds__(256) void colmax_kernel()
{
    int r = blockIdx.y;
    int t = blockIdx.x * 256 + threadIdx.x;
    const float* fmr = g_fm + r * AA * TT;
    float m = fmr[t];
    #pragma unroll 4
    for (int a = 1; a < AA; a++)
        m = fmaxf(m, fmr[a * TT + t]);
    g_cm[r * TT + t] = m;
}

// ---------------- all 16 matched-pursuit steps in one launch ---------------
// Rows are fully independent -> one block per row, no inter-block sync.
__global__ __launch_bounds__(1024) void steps_kernel(const float* __restrict__ atom_emb)
{
    __shared__ float s_rv[32];
    __shared__ int   s_rt[32];
    __shared__ float sh_v;
    __shared__ int   sh_ti, sh_ai, sh_pa, sh_aa;

    int r = blockIdx.x;
    int tid = threadIdx.x;
    int lane = tid & 31, wid = tid >> 5;

    float* cm   = g_cm  + r * TT;
    float* fmr  = g_fm  + r * AA * TT;
    float* resr = g_res + r * TT;

    for (int s = 0; s < NSTEP; s++) {
        // --- global argmax over columns (tie -> lowest t) ---
        float bv = -3.402823466e38f;
        int bt = 0x7fffffff;
        for (int t = tid; t < TT; t += 1024) {   // ascending: strict > keeps lowest t
            float v = cm[t];
            if (v > bv) { bv = v; bt = t; }
        }
        #pragma unroll
        for (int off = 16; off; off >>= 1) {
            float ov = __shfl_down_sync(0xffffffffu, bv, off);
            int   ot = __shfl_down_sync(0xffffffffu, bt, off);
            if (ov > bv || (ov == bv && ot < bt)) { bv = ov; bt = ot; }
        }
        if (lane == 0) { s_rv[wid] = bv; s_rt[wid] = bt; }
        __syncthreads();

        if (wid == 0) {
            bv = s_rv[lane]; bt = s_rt[lane];
            #pragma unroll
            for (int off = 16; off; off >>= 1) {
                float ov = __shfl_down_sync(0xffffffffu, bv, off);
                int   ot = __shfl_down_sync(0xffffffffu, bt, off);
                if (ov > bv || (ov == bv && ot < bt)) { bv = ov; bt = ot; }
            }
            bt = __shfl_sync(0xffffffffu, bt, 0);

            // --- argmax over atoms at winning column (tie -> lowest a) ---
            float av = -3.402823466e38f;
            int aarg = 0x7fffffff;
            for (int a = lane; a < AA; a += 32) {  // ascending per lane
                float v = fmr[a * TT + bt];
                if (v > av) { av = v; aarg = a; }
            }
            #pragma unroll
            for (int off = 16; off; off >>= 1) {
                float ov = __shfl_down_sync(0xffffffffu, av, off);
                int   oa = __shfl_down_sync(0xffffffffu, aarg, off);
                if (ov > av || (ov == av && oa < aarg)) { av = ov; aarg = oa; }
            }
            if (lane == 0) {
                sh_v = av; sh_ti = bt; sh_ai = aarg;
                int pa, aa;
                if (av > 0.f)      { pa = bt; aa = aarg; }
                else if (av < 0.f) { pa = (bt == 0) ? 1 : 0; aa = (aarg == 0) ? 1 : 0; }
                else               { pa = 0; aa = 0; }
                sh_pa = pa; sh_aa = aa;
            }
        }
        __syncthreads();

        float v = sh_v;
        int ti = sh_ti, ai = sh_ai;

        // --- emit embedding row + update residual ---
        if (tid < 128) {
            float e;
            if (tid == 0)      e = (float)sh_pa * (20.f / (float)(TT - 1));
            else if (tid == 1) e = v;
            else               e = atom_emb[sh_aa * EE + (tid - 2)];
            g_emb[(r * NSTEP + s) * 128 + tid] = e;
        } else if (tid < 256) {
            int k = tid - 128;
            int t = ti - 64 + k;
            if (t >= 0 && t < TT) resr[t] -= v * g_du[ai * KK + k];
        }

        // --- incremental fm window update via precomputed xcorr ---
        const float* xcr = g_xc + ai * AA * 256;
        for (int idx = tid; idx < AA * 255; idx += 1024) {
            int a = idx / 255;
            int j = idx - a * 255;
            int t = ti - 127 + j;
            if (t >= 0 && t < TT) fmr[a * TT + t] -= v * xcr[a * 256 + j];
        }
        __syncthreads();

        // --- recompute column max for affected columns ---
        if (tid < 255) {
            int t = ti - 127 + tid;
            if (t >= 0 && t < TT) {
                float m = fmr[t];
                #pragma unroll 4
                for (int a = 1; a < AA; a++)
                    m = fmaxf(m, fmr[a * TT + t]);
                cm[t] = m;
            }
        }
        __syncthreads();
    }
}

// ---------------- final loss ------------------------------------------------
__global__ __launch_bounds__(256) void final_kernel(const float* __restrict__ proj,
                                                    float* __restrict__ out)
{
    __shared__ float sred[8];
    __shared__ float s_norm[4];
    __shared__ float s_keys[64];
    __shared__ int   s_order[64];

    int tid = threadIdx.x; // 256
    int lane = tid & 31, wid = tid >> 5;

    for (int r = 0; r < 4; r++) {
        float ss = 0.f;
        for (int t = tid; t < TT; t += 256) {
            float v = g_res[r * TT + t];
            ss += v * v;
        }
        #pragma unroll
        for (int off = 16; off; off >>= 1)
            ss += __shfl_down_sync(0xffffffffu, ss, off);
        if (lane == 0) sred[wid] = ss;
        __syncthreads();
        if (tid == 0) {
            float t2 = 0.f;
            for (int w = 0; w < 8; w++) t2 += sred[w];
            s_norm[r] = sqrtf(t2);
        }
        __syncthreads();
    }

    if (tid < 64) {
        float k = 0.f;
        const float* e = g_emb + tid * 128;
        for (int j = 0; j < 128; j++) k += e[j] * proj[j];
        s_keys[tid] = k;
    }
    __syncthreads();

    if (tid < 4) {   // stable insertion sort, ascending (matches jnp.argsort)
        int ord[16];
        for (int i = 0; i < 16; i++) ord[i] = i;
        for (int i = 1; i < 16; i++) {
            int oi = ord[i];
            float ki = s_keys[tid * 16 + oi];
            int j = i - 1;
            while (j >= 0 && s_keys[tid * 16 + ord[j]] > ki) { ord[j + 1] = ord[j]; j--; }
            ord[j + 1] = oi;
        }
        for (int i = 0; i < 16; i++) s_order[tid * 16 + i] = ord[i];
    }
    __syncthreads();

    float acc = 0.f;
    for (int i = tid; i < 4096; i += 256) {
        int b = i >> 11;
        int st = (i >> 7) & 15;
        int e = i & 127;
        int sa = s_order[b * 16 + st];
        int sb = s_order[(2 + b) * 16 + st];
        float dd = g_emb[(b * 16 + sa) * 128 + e] - g_emb[((2 + b) * 16 + sb) * 128 + e];
        acc += dd * dd;
    }
    #pragma unroll
    for (int off = 16; off; off >>= 1)
        acc += __shfl_down_sync(0xffffffffu, acc, off);
    if (lane == 0) sred[wid] = acc;
    __syncthreads();
    if (tid == 0) {
        float t2 = 0.f;
        for (int w = 0; w < 8; w++) t2 += sred[w];
        out[0] = t2 / 4096.f
               + 0.5f * (fabsf(s_norm[0] - s_norm[2]) + fabsf(s_norm[1] - s_norm[3]));
    }
}

// ---------------- launch ----------------------------------------------------
extern "C" void kernel_launch(void* const* d_in, const int* in_sizes, int n_in,
                              void* d_out, int out_size)
{
    (void)in_sizes; (void)n_in; (void)out_size;
    const float* a    = (const float*)d_in[0];
    const float* b    = (const float*)d_in[1];
    const float* d    = (const float*)d_in[2];
    const float* aemb = (const float*)d_in[3];
    const float* proj = (const float*)d_in[4];
    float* out = (float*)d_out;

    prep_kernel<<<384, 128>>>(a, b, d);
    corr_kernel<<<dim3(2, 128, 2), 256>>>(1);   // xcorr: 128 rows (ai), 2 tiles, 2 atom halves
    corr_kernel<<<dim3(128, 4, 2), 256>>>(0);   // fm:    4 rows, 128 tiles, 2 atom halves
    colmax_kernel<<<dim3(64, 4), 256>>>();
    steps_kernel<<<4, 1024>>>(aemb);
    final_kernel<<<1, 256>>>(proj, out);
}

// round 2
// speedup vs baseline: 2.0003x; 2.0003x over previous
#include <cuda_runtime.h>
#include <math.h>

#define TT    16384
#define AA    128
#define KK    128
#define NROW  4
#define NSTEP 16
#define EE    126

// ---------------- device scratch (static: no allocations allowed) ----------
__device__ float    g_du[AA * KK];             // normalized dictionary
__device__ float    g_xc[AA * AA * 256];       // atom cross-correlation, stride 256
__device__ float    g_fm[NROW * AA * TT];      // feature maps
__device__ float    g_res[NROW * TT];          // residuals
__device__ unsigned g_cm[NROW * TT];           // per-column max, ORDER-ENCODED uint
__device__ float    g_emb[NROW * NSTEP * 128]; // embeddings per step

// order-preserving float->uint encoding (monotone bijection)
__device__ __forceinline__ unsigned fenc(float f) {
    unsigned u = __float_as_uint(f);
    return (u & 0x80000000u) ? ~u : (u | 0x80000000u);
}

// ---------------- prep: d_unit + residual init + cm init -------------------
__global__ void prep_kernel(const float* __restrict__ a,
                            const float* __restrict__ b,
                            const float* __restrict__ d)
{
    __shared__ float sred[4];
    int bx = blockIdx.x;
    int tid = threadIdx.x; // 128
    if (bx < AA) {
        float v = d[bx * KK + tid];
        float ss = v * v;
        #pragma unroll
        for (int off = 16; off; off >>= 1)
            ss += __shfl_down_sync(0xffffffffu, ss, off);
        if ((tid & 31) == 0) sred[tid >> 5] = ss;
        __syncthreads();
        float tot = sred[0] + sred[1] + sred[2] + sred[3];
        g_du[bx * KK + tid] = v / (sqrtf(tot) + 1e-8f);
    } else {
        int base = (bx - AA) * 256;
        #pragma unroll
        for (int j = tid; j < 256; j += 128) {
            int i = base + j;
            g_res[i] = (i < 2 * TT) ? a[i] : b[i - 2 * TT];
            g_cm[i] = 0u;   // below encode(-inf)=0x007fffff
        }
    }
}

// ---------------- merged correlation kernel (fm + xcorr), f32x2 ------------
// blk <  1024 : fm    (row 0..3, tile 0..127, half 0..1)
// blk >= 1024 : xcorr (row 0..127, tile 0..1, half 0..1)
__global__ __launch_bounds__(256) void corr_kernel()
{
    __shared__ float s_du[KK][64];   // [k][a_local] 32KB
    __shared__ float s_sig[256];
    __shared__ float s_red[8][128];  // colmax epilogue

    int blk = blockIdx.x;
    int tid = threadIdx.x; // 256

    int mode, row, tile, half;
    if (blk < 1024) { mode = 0; half = blk & 1; row = (blk >> 1) & 3; tile = blk >> 3; }
    else { int b2 = blk - 1024; mode = 1; half = b2 & 1; tile = (b2 >> 1) & 1; row = b2 >> 2; }
    int t0 = tile * 128;

    for (int i = tid; i < 64 * KK; i += 256) {
        int al = i >> 7, k = i & 127;
        s_du[k][al] = g_du[(half * 64 + al) * KK + k];
    }

    const float* src;
    float* out;
    int srcLen, shift, outStride;
    if (mode == 0) {
        src = g_res + row * TT; srcLen = TT; shift = 64;
        out = g_fm + row * AA * TT; outStride = TT;
    } else {
        src = g_du + row * KK; srcLen = KK; shift = 127;
        out = g_xc + row * AA * 256; outStride = 256;
    }

    {
        int t = t0 + tid - shift;
        s_sig[tid] = (t >= 0 && t < srcLen) ? src[t] : 0.f;
    }
    __syncthreads();

    int x = tid & 31, y = tid >> 5;
    int c0 = x * 4, a0 = y * 8;

    // acc2[j][c]: packed pair of atoms (a0+2j, a0+2j+1) at column c0+c
    unsigned long long acc2[4][4];
    #pragma unroll
    for (int j = 0; j < 4; j++)
        #pragma unroll
        for (int c = 0; c < 4; c++) acc2[j][c] = 0ull;

    unsigned r0 = __float_as_uint(s_sig[c0]);
    unsigned r1 = __float_as_uint(s_sig[c0 + 1]);
    unsigned r2 = __float_as_uint(s_sig[c0 + 2]);
    unsigned r3 = __float_as_uint(s_sig[c0 + 3]);

    #pragma unroll 4
    for (int k = 0; k < KK; k++) {
        unsigned long long dv[4];
        #pragma unroll
        for (int j = 0; j < 4; j++)
            dv[j] = *(const unsigned long long*)&s_du[k][a0 + 2 * j];

        unsigned long long rr0, rr1, rr2, rr3;
        asm("mov.b64 %0, {%1, %1};" : "=l"(rr0) : "r"(r0));
        asm("mov.b64 %0, {%1, %1};" : "=l"(rr1) : "r"(r1));
        asm("mov.b64 %0, {%1, %1};" : "=l"(rr2) : "r"(r2));
        asm("mov.b64 %0, {%1, %1};" : "=l"(rr3) : "r"(r3));

        #pragma unroll
        for (int j = 0; j < 4; j++) {
            asm("fma.rn.f32x2 %0, %1, %2, %0;" : "+l"(acc2[j][0]) : "l"(dv[j]), "l"(rr0));
            asm("fma.rn.f32x2 %0, %1, %2, %0;" : "+l"(acc2[j][1]) : "l"(dv[j]), "l"(rr1));
            asm("fma.rn.f32x2 %0, %1, %2, %0;" : "+l"(acc2[j][2]) : "l"(dv[j]), "l"(rr2));
            asm("fma.rn.f32x2 %0, %1, %2, %0;" : "+l"(acc2[j][3]) : "l"(dv[j]), "l"(rr3));
        }
        r0 = r1; r1 = r2; r2 = r3;
        r3 = __float_as_uint(s_sig[c0 + 4 + k]);   // max index 255, in bounds
    }

    int a_base = half * 64 + a0;
    int t = t0 + c0;
    float cmax[4] = { -3.402823466e38f, -3.402823466e38f,
                      -3.402823466e38f, -3.402823466e38f };
    #pragma unroll
    for (int j = 0; j < 4; j++) {
        float lo[4], hi[4];
        #pragma unroll
        for (int c = 0; c < 4; c++) {
            lo[c] = __uint_as_float((unsigned)acc2[j][c]);
            hi[c] = __uint_as_float((unsigned)(acc2[j][c] >> 32));
            cmax[c] = fmaxf(cmax[c], fmaxf(lo[c], hi[c]));
        }
        *(float4*)(out + (a_base + 2 * j) * outStride + t) =
            make_float4(lo[0], lo[1], lo[2], lo[3]);
        *(float4*)(out + (a_base + 2 * j + 1) * outStride + t) =
            make_float4(hi[0], hi[1], hi[2], hi[3]);
    }

    if (mode == 0) {
        #pragma unroll
        for (int c = 0; c < 4; c++) s_red[y][c0 + c] = cmax[c];
        __syncthreads();
        if (tid < 128) {
            float m = s_red[0][tid];
            #pragma unroll
            for (int w = 1; w < 8; w++) m = fmaxf(m, s_red[w][tid]);
            atomicMax(&g_cm[row * TT + t0 + tid], fenc(m));
        }
    }
}

// ---------------- all 16 matched-pursuit steps in one launch ---------------
__global__ __launch_bounds__(1024) void steps_kernel(const float* __restrict__ atom_emb)
{
    __shared__ unsigned s_rk[32];
    __shared__ int      s_rt[32];
    __shared__ float sh_v;
    __shared__ int   sh_ti, sh_ai, sh_pa, sh_aa;

    int r = blockIdx.x;
    int tid = threadIdx.x;
    int lane = tid & 31, wid = tid >> 5;

    unsigned* cm   = g_cm  + r * TT;
    float*    fmr  = g_fm  + r * AA * TT;
    float*    resr = g_res + r * TT;

    for (int s = 0; s < NSTEP; s++) {
        // --- phase 1: global argmax over encoded cm (tie -> lowest t) ---
        unsigned bk = 0u;
        int bt = 0x7fffffff;
        const uint4* cm4 = (const uint4*)cm + tid * 4;   // 16 cols per thread, blocked
        #pragma unroll
        for (int q = 0; q < 4; q++) {
            uint4 u = cm4[q];
            int tb = tid * 16 + q * 4;
            if (u.x > bk) { bk = u.x; bt = tb; }
            if (u.y > bk) { bk = u.y; bt = tb + 1; }
            if (u.z > bk) { bk = u.z; bt = tb + 2; }
            if (u.w > bk) { bk = u.w; bt = tb + 3; }
        }
        #pragma unroll
        for (int off = 16; off; off >>= 1) {
            unsigned ok = __shfl_down_sync(0xffffffffu, bk, off);
            int      ot = __shfl_down_sync(0xffffffffu, bt, off);
            if (ok > bk || (ok == bk && ot < bt)) { bk = ok; bt = ot; }
        }
        if (lane == 0) { s_rk[wid] = bk; s_rt[wid] = bt; }
        __syncthreads();

        // --- phase 2: warp 0 final reduce + atom argmax at winning column ---
        if (wid == 0) {
            bk = s_rk[lane]; bt = s_rt[lane];
            #pragma unroll
            for (int off = 16; off; off >>= 1) {
                unsigned ok = __shfl_down_sync(0xffffffffu, bk, off);
                int      ot = __shfl_down_sync(0xffffffffu, bt, off);
                if (ok > bk || (ok == bk && ot < bt)) { bk = ok; bt = ot; }
            }
            bt = __shfl_sync(0xffffffffu, bt, 0);

            float av = -3.402823466e38f;
            int aarg = 0x7fffffff;
            #pragma unroll
            for (int a = lane; a < AA; a += 32) {     // ascending per lane
                float fv = fmr[a * TT + bt];
                if (fv > av) { av = fv; aarg = a; }
            }
            #pragma unroll
            for (int off = 16; off; off >>= 1) {
                float ov = __shfl_down_sync(0xffffffffu, av, off);
                int   oa = __shfl_down_sync(0xffffffffu, aarg, off);
                if (ov > av || (ov == av && oa < aarg)) { av = ov; aarg = oa; }
            }
            if (lane == 0) {
                sh_v = av; sh_ti = bt; sh_ai = aarg;
                int pa, aa;
                if (av > 0.f)      { pa = bt; aa = aarg; }
                else if (av < 0.f) { pa = (bt == 0) ? 1 : 0; aa = (aarg == 0) ? 1 : 0; }
                else               { pa = 0; aa = 0; }
                sh_pa = pa; sh_aa = aa;
            }
        }
        __syncthreads();

        float v = sh_v;
        int ti = sh_ti, ai = sh_ai;

        // --- phase 3a: embedding + residual update (low threads, cheap) ---
        if (tid < 128) {
            float e;
            if (tid == 0)      e = (float)sh_pa * (20.f / (float)(TT - 1));
            else if (tid == 1) e = v;
            else               e = atom_emb[sh_aa * EE + (tid - 2)];
            g_emb[(r * NSTEP + s) * 128 + tid] = e;
        } else if (tid < 256) {
            int k = tid - 128;
            int t = ti - 64 + k;
            if (t >= 0 && t < TT) resr[t] -= v * g_du[ai * KK + k];
        }

        // --- phase 3b: fused fm window update + colmax recompute ---
        // 4 threads per column, 32 atoms each; quad shfl reduce -> cm
        {
            int col = tid >> 2, sub = tid & 3;
            int t = ti - 127 + col;
            bool valid = (col < 255) && (t >= 0) && (t < TT);
            float m = -3.402823466e38f;
            if (valid) {
                float*       fp = fmr + (sub * 32) * TT + t;
                const float* xp = g_xc + (ai * AA + sub * 32) * 256 + col;
                #pragma unroll 8
                for (int i = 0; i < 32; i++) {
                    float f = fp[i * TT] - v * xp[i * 256];
                    fp[i * TT] = f;
                    m = fmaxf(m, f);
                }
            }
            m = fmaxf(m, __shfl_xor_sync(0xffffffffu, m, 1));
            m = fmaxf(m, __shfl_xor_sync(0xffffffffu, m, 2));
            if (valid && sub == 0) cm[t] = fenc(m);
        }
        __syncthreads();
    }
}

// ---------------- final loss ------------------------------------------------
__global__ __launch_bounds__(256) void final_kernel(const float* __restrict__ proj,
                                                    float* __restrict__ out)
{
    __shared__ float sred[8];
    __shared__ float s_norm[4];
    __shared__ float s_keys[64];
    __shared__ int   s_order[64];

    int tid = threadIdx.x; // 256
    int lane = tid & 31, wid = tid >> 5;

    for (int r = 0; r < 4; r++) {
        float ss = 0.f;
        for (int t = tid; t < TT; t += 256) {
            float v = g_res[r * TT + t];
            ss += v * v;
        }
        #pragma unroll
        for (int off = 16; off; off >>= 1)
            ss += __shfl_down_sync(0xffffffffu, ss, off);
        if (lane == 0) sred[wid] = ss;
        __syncthreads();
        if (tid == 0) {
            float t2 = 0.f;
            for (int w = 0; w < 8; w++) t2 += sred[w];
            s_norm[r] = sqrtf(t2);
        }
        __syncthreads();
    }

    if (tid < 64) {
        float k = 0.f;
        const float* e = g_emb + tid * 128;
        for (int j = 0; j < 128; j++) k += e[j] * proj[j];
        s_keys[tid] = k;
    }
    __syncthreads();

    if (tid < 4) {   // stable insertion sort, ascending (matches jnp.argsort)
        int ord[16];
        for (int i = 0; i < 16; i++) ord[i] = i;
        for (int i = 1; i < 16; i++) {
            int oi = ord[i];
            float ki = s_keys[tid * 16 + oi];
            int j = i - 1;
            while (j >= 0 && s_keys[tid * 16 + ord[j]] > ki) { ord[j + 1] = ord[j]; j--; }
            ord[j + 1] = oi;
        }
        for (int i = 0; i < 16; i++) s_order[tid * 16 + i] = ord[i];
    }
    __syncthreads();

    float acc = 0.f;
    for (int i = tid; i < 4096; i += 256) {
        int b = i >> 11;
        int st = (i >> 7) & 15;
        int e = i & 127;
        int sa = s_order[b * 16 + st];
        int sb = s_order[(2 + b) * 16 + st];
        float dd = g_emb[(b * 16 + sa) * 128 + e] - g_emb[((2 + b) * 16 + sb) * 128 + e];
        acc += dd * dd;
    }
    #pragma unroll
    for (int off = 16; off; off >>= 1)
        acc += __shfl_down_sync(0xffffffffu, acc, off);
    if (lane == 0) sred[wid] = acc;
    __syncthreads();
    if (tid == 0) {
        float t2 = 0.f;
        for (int w = 0; w < 8; w++) t2 += sred[w];
        out[0] = t2 / 4096.f
               + 0.5f * (fabsf(s_norm[0] - s_norm[2]) + fabsf(s_norm[1] - s_norm[3]));
    }
}

// ---------------- launch ----------------------------------------------------
extern "C" void kernel_launch(void* const* d_in, const int* in_sizes, int n_in,
                              void* d_out, int out_size)
{
    (void)in_sizes; (void)n_in; (void)out_size;
    const float* a    = (const float*)d_in[0];
    const float* b    = (const float*)d_in[1];
    const float* d    = (const float*)d_in[2];
    const float* aemb = (const float*)d_in[3];
    const float* proj = (const float*)d_in[4];
    float* out = (float*)d_out;

    prep_kernel<<<384, 128>>>(a, b, d);
    corr_kernel<<<1536, 256>>>();          // fm (1024 blocks) + xcorr (512 blocks)
    steps_kernel<<<4, 1024>>>(aemb);
    final_kernel<<<1, 256>>>(proj, out);
}

// round 3
// speedup vs baseline: 2.6371x; 1.3184x over previous
#include <cuda_runtime.h>
#include <math.h>

#define TT    16384
#define AA    128
#define KK    128
#define NROW  4
#define NSTEP 16
#define EE    126
#define XSTR  260      // padded xc4 row stride in floats (multiple of 4)

// ---------------- device scratch (static: no allocations allowed) ----------
__device__ __align__(16) float    g_du[AA * KK];
__device__ __align__(16) float    g_xc4[AA * 4 * AA * XSTR]; // [ai][shift][a][j'] ~68MB
__device__ __align__(16) float    g_fm[NROW * AA * TT];
__device__ __align__(16) float    g_res[NROW * TT];
__device__ __align__(16) unsigned g_cm[NROW * TT];           // encoded colmax (init)
__device__ __align__(16) float    g_emb[NROW * NSTEP * 128];
__device__ float                  g_norm[NROW];

// order-preserving float->uint encoding (monotone bijection)
__device__ __forceinline__ unsigned fenc(float f) {
    unsigned u = __float_as_uint(f);
    return (u & 0x80000000u) ? ~u : (u | 0x80000000u);
}

// ---------------- prep: d_unit + residual/cm init + xc4 edge zero ----------
__global__ void prep_kernel(const float* __restrict__ a,
                            const float* __restrict__ b,
                            const float* __restrict__ d)
{
    __shared__ float sred[4];
    int bx = blockIdx.x;
    int tid = threadIdx.x; // 128
    if (bx < AA) {
        float v = d[bx * KK + tid];
        float ss = v * v;
        #pragma unroll
        for (int off = 16; off; off >>= 1)
            ss += __shfl_down_sync(0xffffffffu, ss, off);
        if ((tid & 31) == 0) sred[tid >> 5] = ss;
        __syncthreads();
        float tot = sred[0] + sred[1] + sred[2] + sred[3];
        g_du[bx * KK + tid] = v / (sqrtf(tot) + 1e-8f);
    } else if (bx < 384) {
        int base = (bx - AA) * 256;
        #pragma unroll
        for (int j = tid; j < 256; j += 128) {
            int i = base + j;
            g_res[i] = (i < 2 * TT) ? a[i] : b[i - 2 * TT];
            g_cm[i] = 0u;
        }
    } else {
        // zero uncovered edges of g_xc4: for shift s, cols [0,s) and [256+s,260)
        int bb = bx - 384;           // 0..511
        int ai = bb >> 2, s = bb & 3;
        int aa2 = tid;               // atom
        #pragma unroll
        for (int idx = 0; idx < 4; idx++) {
            int jp = (idx < s) ? idx : 256 + idx;
            g_xc4[((ai * 4 + s) * AA + aa2) * XSTR + jp] = 0.f;
        }
    }
}

// ---------------- merged correlation kernel (fm + xcorr), f32x2 ------------
// blk <  1024 : fm    (row 0..3, tile 0..127, half 0..1) -> g_fm + colmax
// blk >= 1024 : xcorr (row 0..127, tile 0..1, half 0..1) -> g_xc4 (4 shifts)
__global__ __launch_bounds__(256) void corr_kernel()
{
    __shared__ float s_du[KK][64];   // [k][a_local] 32KB
    __shared__ float s_sig[256];
    __shared__ float s_red[8][128];  // colmax epilogue

    int blk = blockIdx.x;
    int tid = threadIdx.x; // 256

    int mode, row, tile, half;
    if (blk < 1024) { mode = 0; half = blk & 1; row = (blk >> 1) & 3; tile = blk >> 3; }
    else { int b2 = blk - 1024; mode = 1; half = b2 & 1; tile = (b2 >> 1) & 1; row = b2 >> 2; }
    int t0 = tile * 128;

    for (int i = tid; i < 64 * KK; i += 256) {
        int al = i >> 7, k = i & 127;
        s_du[k][al] = g_du[(half * 64 + al) * KK + k];
    }

    const float* src;
    int srcLen, shift;
    if (mode == 0) { src = g_res + row * TT; srcLen = TT; shift = 64; }
    else           { src = g_du + row * KK;  srcLen = KK; shift = 127; }

    {
        int t = t0 + tid - shift;
        s_sig[tid] = (t >= 0 && t < srcLen) ? src[t] : 0.f;
    }
    __syncthreads();

    int x = tid & 31, y = tid >> 5;
    int c0 = x * 4, a0 = y * 8;

    unsigned long long acc2[4][4];
    #pragma unroll
    for (int j = 0; j < 4; j++)
        #pragma unroll
        for (int c = 0; c < 4; c++) acc2[j][c] = 0ull;

    unsigned r0 = __float_as_uint(s_sig[c0]);
    unsigned r1 = __float_as_uint(s_sig[c0 + 1]);
    unsigned r2 = __float_as_uint(s_sig[c0 + 2]);
    unsigned r3 = __float_as_uint(s_sig[c0 + 3]);

    #pragma unroll 4
    for (int k = 0; k < KK; k++) {
        unsigned long long dv[4];
        #pragma unroll
        for (int j = 0; j < 4; j++)
            dv[j] = *(const unsigned long long*)&s_du[k][a0 + 2 * j];

        unsigned long long rr0, rr1, rr2, rr3;
        asm("mov.b64 %0, {%1, %1};" : "=l"(rr0) : "r"(r0));
        asm("mov.b64 %0, {%1, %1};" : "=l"(rr1) : "r"(r1));
        asm("mov.b64 %0, {%1, %1};" : "=l"(rr2) : "r"(r2));
        asm("mov.b64 %0, {%1, %1};" : "=l"(rr3) : "r"(r3));

        #pragma unroll
        for (int j = 0; j < 4; j++) {
            asm("fma.rn.f32x2 %0, %1, %2, %0;" : "+l"(acc2[j][0]) : "l"(dv[j]), "l"(rr0));
            asm("fma.rn.f32x2 %0, %1, %2, %0;" : "+l"(acc2[j][1]) : "l"(dv[j]), "l"(rr1));
            asm("fma.rn.f32x2 %0, %1, %2, %0;" : "+l"(acc2[j][2]) : "l"(dv[j]), "l"(rr2));
            asm("fma.rn.f32x2 %0, %1, %2, %0;" : "+l"(acc2[j][3]) : "l"(dv[j]), "l"(rr3));
        }
        r0 = r1; r1 = r2; r2 = r3;
        r3 = __float_as_uint(s_sig[c0 + 4 + k]);
    }

    int a_base = half * 64 + a0;
    int t = t0 + c0;

    if (mode == 0) {
        float* out = g_fm + row * AA * TT;
        float cmax[4] = { -3.402823466e38f, -3.402823466e38f,
                          -3.402823466e38f, -3.402823466e38f };
        #pragma unroll
        for (int j = 0; j < 4; j++) {
            float lo[4], hi[4];
            #pragma unroll
            for (int c = 0; c < 4; c++) {
                lo[c] = __uint_as_float((unsigned)acc2[j][c]);
                hi[c] = __uint_as_float((unsigned)(acc2[j][c] >> 32));
                cmax[c] = fmaxf(cmax[c], fmaxf(lo[c], hi[c]));
            }
            *(float4*)(out + (a_base + 2 * j) * TT + t) =
                make_float4(lo[0], lo[1], lo[2], lo[3]);
            *(float4*)(out + (a_base + 2 * j + 1) * TT + t) =
                make_float4(hi[0], hi[1], hi[2], hi[3]);
        }
        #pragma unroll
        for (int c = 0; c < 4; c++) s_red[y][c0 + c] = cmax[c];
        __syncthreads();
        if (tid < 128) {
            float m = s_red[0][tid];
            #pragma unroll
            for (int w = 1; w < 8; w++) m = fmaxf(m, s_red[w][tid]);
            atomicMax(&g_cm[row * TT + t0 + tid], fenc(m));
        }
    } else {
        // write 4 shifted copies: g_xc4[row][s][a][j + s] = xcorr[row][a][j]
        #pragma unroll
        for (int j = 0; j < 4; j++) {
            #pragma unroll
            for (int c = 0; c < 4; c++) {
                float lov = __uint_as_float((unsigned)acc2[j][c]);
                float hiv = __uint_as_float((unsigned)(acc2[j][c] >> 32));
                int jj = t + c;
                #pragma unroll
                for (int s = 0; s < 4; s++) {
                    long base = ((long)(row * 4 + s) * AA + a_base + 2 * j) * XSTR + jj + s;
                    g_xc4[base] = lov;
                    g_xc4[base + XSTR] = hiv;
                }
            }
        }
    }
}

// ---------------- all 16 matched-pursuit steps in one launch ---------------
// dynamic smem: s_cm (TT uints, 64KB) + s_tile (AA*XSTR floats, 133KB)
__global__ __launch_bounds__(1024) void steps_kernel(const float* __restrict__ atom_emb)
{
    extern __shared__ unsigned char smem_raw[];
    unsigned* s_cm = (unsigned*)smem_raw;
    float* s_tile = (float*)(smem_raw + TT * sizeof(unsigned));

    __shared__ unsigned s_rk[32];
    __shared__ int      s_rt[32];
    __shared__ float    s_nred[32];
    __shared__ float sh_v;
    __shared__ int   sh_ti, sh_ai, sh_pa, sh_aa;

    int r = blockIdx.x;
    int tid = threadIdx.x;
    int lane = tid & 31, wid = tid >> 5;

    float* fmr  = g_fm  + r * AA * TT;
    float* resr = g_res + r * TT;

    // load initial colmax into smem
    #pragma unroll
    for (int q = 0; q < 4; q++)
        ((uint4*)s_cm)[tid + 1024 * q] = ((const uint4*)(g_cm + r * TT))[tid + 1024 * q];
    __syncthreads();

    for (int step = 0; step < NSTEP; step++) {
        // --- phase 1: global argmax over encoded s_cm (tie -> lowest t) ---
        unsigned bk = 0u;
        int bt = 0x7fffffff;
        #pragma unroll
        for (int q = 0; q < 4; q++) {
            uint4 u = ((const uint4*)s_cm)[tid + 1024 * q];
            int tb = (tid + 1024 * q) * 4;
            if (u.x > bk) { bk = u.x; bt = tb; }
            if (u.y > bk) { bk = u.y; bt = tb + 1; }
            if (u.z > bk) { bk = u.z; bt = tb + 2; }
            if (u.w > bk) { bk = u.w; bt = tb + 3; }
        }
        #pragma unroll
        for (int off = 16; off; off >>= 1) {
            unsigned ok = __shfl_down_sync(0xffffffffu, bk, off);
            int      ot = __shfl_down_sync(0xffffffffu, bt, off);
            if (ok > bk || (ok == bk && ot < bt)) { bk = ok; bt = ot; }
        }
        if (lane == 0) { s_rk[wid] = bk; s_rt[wid] = bt; }
        __syncthreads();

        // --- phase 2: warp 0 final reduce + atom argmax at winning column ---
        if (wid == 0) {
            bk = s_rk[lane]; bt = s_rt[lane];
            #pragma unroll
            for (int off = 16; off; off >>= 1) {
                unsigned ok = __shfl_down_sync(0xffffffffu, bk, off);
                int      ot = __shfl_down_sync(0xffffffffu, bt, off);
                if (ok > bk || (ok == bk && ot < bt)) { bk = ok; bt = ot; }
            }
            bt = __shfl_sync(0xffffffffu, bt, 0);

            float av = -3.402823466e38f;
            int aarg = 0x7fffffff;
            #pragma unroll
            for (int a = lane; a < AA; a += 32) {
                float fv = fmr[a * TT + bt];
                if (fv > av) { av = fv; aarg = a; }
            }
            #pragma unroll
            for (int off = 16; off; off >>= 1) {
                float ov = __shfl_down_sync(0xffffffffu, av, off);
                int   oa = __shfl_down_sync(0xffffffffu, aarg, off);
                if (ov > av || (ov == av && oa < aarg)) { av = ov; aarg = oa; }
            }
            if (lane == 0) {
                sh_v = av; sh_ti = bt; sh_ai = aarg;
                int pa, aa2;
                if (av > 0.f)      { pa = bt; aa2 = aarg; }
                else if (av < 0.f) { pa = (bt == 0) ? 1 : 0; aa2 = (aarg == 0) ? 1 : 0; }
                else               { pa = 0; aa2 = 0; }
                sh_pa = pa; sh_aa = aa2;
            }
        }
        __syncthreads();

        float v = sh_v;
        int ti = sh_ti, ai = sh_ai;
        int w0  = (ti - 127) & ~3;        // aligned window start
        int shf = (ti - 127) - w0;        // 0..3

        // --- phase 3a: embedding, residual update, s_cm window reset ---
        if (tid < 128) {
            float e;
            if (tid == 0)      e = (float)sh_pa * (20.f / (float)(TT - 1));
            else if (tid == 1) e = v;
            else               e = atom_emb[sh_aa * EE + (tid - 2)];
            g_emb[(r * NSTEP + step) * 128 + tid] = e;
        } else if (tid < 256) {
            int k = tid - 128;
            int t = ti - 64 + k;
            if (t >= 0 && t < TT) resr[t] -= v * g_du[ai * KK + k];
        } else if (tid < 516) {
            int c = tid - 256;            // 0..259
            int t = w0 + c;
            if (t >= 0 && t < TT) s_cm[t] = 0u;
        }

        // --- phase 3b: coalesced float4 window update (fm gmem + smem tile)
        {
            #pragma unroll
            for (int ii = 0; ii < 4; ii++) {
                int a = wid * 4 + ii;
                float*       fp = fmr + a * TT;
                const float* xp = g_xc4 + ((long)(ai * 4 + shf) * AA + a) * XSTR;
                float*       tp = s_tile + a * XSTR;
                #pragma unroll
                for (int it = 0; it < 3; it++) {
                    int jj4 = lane + 32 * it;
                    if (jj4 < 65) {
                        int jp = jj4 * 4;
                        int t = w0 + jp;
                        if (t >= 0 && t + 3 < TT) {
                            float4 f = *(const float4*)(fp + t);
                            float4 xx = *(const float4*)(xp + jp);
                            f.x -= v * xx.x; f.y -= v * xx.y;
                            f.z -= v * xx.z; f.w -= v * xx.w;
                            *(float4*)(fp + t) = f;
                            *(float4*)(tp + jp) = f;
                        } else {
                            #pragma unroll
                            for (int e = 0; e < 4; e++) {
                                int te = t + e;
                                if (te >= 0 && te < TT) {
                                    float f = fp[te] - v * xp[jp + e];
                                    fp[te] = f;
                                    tp[jp + e] = f;
                                }
                            }
                        }
                    }
                }
            }
        }
        __syncthreads();

        // --- phase 4: colmax recompute from smem tile -> atomicMax s_cm ---
        {
            int c4 = tid & 63, sub = tid >> 6;      // 16 subs x 8 atoms, c4<64
            #pragma unroll
            for (int pass = 0; pass < 2; pass++) {
                int cc4, ss;
                if (pass == 0) { cc4 = c4; ss = sub; }
                else { if (tid >= 16) break; cc4 = 64; ss = tid; }
                float m0 = -3.402823466e38f, m1 = m0, m2 = m0, m3 = m0;
                #pragma unroll
                for (int i = 0; i < 8; i++) {
                    int a = ss * 8 + i;
                    float4 xx = *(const float4*)(s_tile + a * XSTR + 4 * cc4);
                    m0 = fmaxf(m0, xx.x); m1 = fmaxf(m1, xx.y);
                    m2 = fmaxf(m2, xx.z); m3 = fmaxf(m3, xx.w);
                }
                int tb = w0 + 4 * cc4;
                if (tb >= 0     && tb < TT)     atomicMax(&s_cm[tb],     fenc(m0));
                if (tb + 1 >= 0 && tb + 1 < TT) atomicMax(&s_cm[tb + 1], fenc(m1));
                if (tb + 2 >= 0 && tb + 2 < TT) atomicMax(&s_cm[tb + 2], fenc(m2));
                if (tb + 3 >= 0 && tb + 3 < TT) atomicMax(&s_cm[tb + 3], fenc(m3));
            }
        }
        __syncthreads();
    }

    // --- residual norm (fused) ---
    float ss = 0.f;
    #pragma unroll
    for (int q = 0; q < 4; q++) {
        float4 vv = ((const float4*)resr)[tid + 1024 * q];
        ss += vv.x * vv.x + vv.y * vv.y + vv.z * vv.z + vv.w * vv.w;
    }
    #pragma unroll
    for (int off = 16; off; off >>= 1)
        ss += __shfl_down_sync(0xffffffffu, ss, off);
    if (lane == 0) s_nred[wid] = ss;
    __syncthreads();
    if (wid == 0) {
        float t2 = s_nred[lane];
        #pragma unroll
        for (int off = 16; off; off >>= 1)
            t2 += __shfl_down_sync(0xffffffffu, t2, off);
        if (lane == 0) g_norm[r] = sqrtf(t2);
    }
}

// ---------------- final loss ------------------------------------------------
__global__ __launch_bounds__(256) void final_kernel(const float* __restrict__ proj,
                                                    float* __restrict__ out)
{
    __shared__ float sred[8];
    __shared__ float s_keys[64];
    __shared__ int   s_order[64];
    __shared__ float s_proj[128];

    int tid = threadIdx.x; // 256
    int lane = tid & 31, wid = tid >> 5;

    if (tid < 128) s_proj[tid] = proj[tid];
    __syncthreads();

    // keys: 8 warps x 8 keys, warp-parallel dot products
    #pragma unroll
    for (int kk = 0; kk < 8; kk++) {
        int key = wid * 8 + kk;
        const float* e = g_emb + key * 128;
        float p = 0.f;
        #pragma unroll
        for (int q = 0; q < 4; q++) {
            int j = lane + 32 * q;
            p += e[j] * s_proj[j];
        }
        #pragma unroll
        for (int off = 16; off; off >>= 1)
            p += __shfl_down_sync(0xffffffffu, p, off);
        if (lane == 0) s_keys[key] = p;
    }
    __syncthreads();

    if (tid < 4) {   // stable insertion sort, ascending (matches jnp.argsort)
        int ord[16];
        for (int i = 0; i < 16; i++) ord[i] = i;
        for (int i = 1; i < 16; i++) {
            int oi = ord[i];
            float ki = s_keys[tid * 16 + oi];
            int j = i - 1;
            while (j >= 0 && s_keys[tid * 16 + ord[j]] > ki) { ord[j + 1] = ord[j]; j--; }
            ord[j + 1] = oi;
        }
        for (int i = 0; i < 16; i++) s_order[tid * 16 + i] = ord[i];
    }
    __syncthreads();

    float acc = 0.f;
    for (int i = tid; i < 4096; i += 256) {
        int b = i >> 11;
        int st = (i >> 7) & 15;
        int e = i & 127;
        int sa = s_order[b * 16 + st];
        int sb = s_order[(2 + b) * 16 + st];
        float dd = g_emb[(b * 16 + sa) * 128 + e] - g_emb[((2 + b) * 16 + sb) * 128 + e];
        acc += dd * dd;
    }
    #pragma unroll
    for (int off = 16; off; off >>= 1)
        acc += __shfl_down_sync(0xffffffffu, acc, off);
    if (lane == 0) sred[wid] = acc;
    __syncthreads();
    if (tid == 0) {
        float t2 = 0.f;
        for (int w = 0; w < 8; w++) t2 += sred[w];
        out[0] = t2 / 4096.f
               + 0.5f * (fabsf(g_norm[0] - g_norm[2]) + fabsf(g_norm[1] - g_norm[3]));
    }
}

// ---------------- launch ----------------------------------------------------
#define SMEM_STEPS (TT * 4 + AA * XSTR * 4)   // 65536 + 133120 = 198656 bytes

extern "C" void kernel_launch(void* const* d_in, const int* in_sizes, int n_in,
                              void* d_out, int out_size)
{
    (void)in_sizes; (void)n_in; (void)out_size;
    const float* a    = (const float*)d_in[0];
    const float* b    = (const float*)d_in[1];
    const float* d    = (const float*)d_in[2];
    const float* aemb = (const float*)d_in[3];
    const float* proj = (const float*)d_in[4];
    float* out = (float*)d_out;

    cudaFuncSetAttribute(steps_kernel,
                         cudaFuncAttributeMaxDynamicSharedMemorySize, SMEM_STEPS);

    prep_kernel<<<896, 128>>>(a, b, d);
    corr_kernel<<<1536, 256>>>();                 // fm (1024) + xcorr->xc4 (512)
    steps_kernel<<<4, 1024, SMEM_STEPS>>>(aemb);
    final_kernel<<<1, 256>>>(proj, out);
}